// round 7
// baseline (speedup 1.0000x reference)
#include <cuda_runtime.h>
#include <cuda_fp16.h>

#define N_NODES 50000
#define N_EDGES 800000
#define F_IN 128
#define HID 160
#define OUT_C 128
#define NGR 64
#define OUT_DIM 10
#define SCAN_NB 49       // ceil(50000/1024)

// ---------------- static scratch (no allocations allowed) ----------------
__device__ int    d_indeg[N_NODES];
__device__ int    d_ptr[N_NODES + 1];
__device__ int    d_cursor[N_NODES];
__device__ float  d_dinv[N_NODES];
__device__ int2   d_edge[N_EDGES];       // {src, norm as float bits}
__device__ uint4  d_Hh0[N_NODES * 2];    // 16 halves per node = 32B row
__device__ uint4  d_Hh1[N_NODES * 2];
__device__ float  d_c5[N_NODES];
__device__ float  d_c10[N_NODES];
__device__ float  d_P3[HID * OUT_DIM];   // W3 @ fc_w   (160x10)
__device__ float  d_P2[HID * OUT_DIM];   // W2 @ P3     (160x10)
__device__ float  d_R [F_IN * OUT_DIM];  // W1 @ P2     (128x10)
__device__ float  d_g1[OUT_DIM];         // b1 @ P2
__device__ float  d_g2[OUT_DIM];         // b2 @ P3
__device__ float  d_g3[OUT_DIM];         // b3 @ fc_w
__device__ float  d_pooled[NGR * OUT_DIM];
__device__ int    d_counts[NGR];
__device__ int    d_bsum[64];

// ---------------- preprocessing ----------------
__global__ void k_zero_deg() {
    int i = blockIdx.x * blockDim.x + threadIdx.x;
    if (i < N_NODES) d_indeg[i] = 0;
}

// vectorized degree histogram (N_EDGES % 4 == 0)
__global__ void k_deg(const int* __restrict__ ei) {
    int e4 = blockIdx.x * blockDim.x + threadIdx.x;
    if (e4 * 4 < N_EDGES) {
        int4 d = *(const int4*)&ei[N_EDGES + e4 * 4];
        atomicAdd(&d_indeg[d.x], 1);
        atomicAdd(&d_indeg[d.y], 1);
        atomicAdd(&d_indeg[d.z], 1);
        atomicAdd(&d_indeg[d.w], 1);
    }
}

// block-local exclusive scan (int4 + warp shuffles), fused dinv computation.
// 256 threads x 4 elems = 1024 elems/block, 49 blocks.
__global__ void k_scan1() {
    __shared__ int wsums[8];
    int tid = threadIdx.x;
    int base = blockIdx.x * 1024 + tid * 4;
    int4 v = make_int4(0, 0, 0, 0);
    if (base < N_NODES) v = *(const int4*)&d_indeg[base];   // base%4==0 -> full int4 in range

    int s0 = v.x, s1 = s0 + v.y, s2 = s1 + v.z, s3 = s2 + v.w;

    int lane = tid & 31, wid = tid >> 5;
    int ws = s3;                                  // warp-inclusive scan of thread sums
    #pragma unroll
    for (int off = 1; off < 32; off <<= 1) {
        int n = __shfl_up_sync(0xffffffffu, ws, off);
        if (lane >= off) ws += n;
    }
    if (lane == 31) wsums[wid] = ws;
    __syncthreads();
    if (wid == 0) {
        int xv = (lane < 8) ? wsums[lane] : 0;
        #pragma unroll
        for (int off = 1; off < 8; off <<= 1) {
            int n = __shfl_up_sync(0xffffffffu, xv, off);
            if (lane >= off) xv += n;
        }
        if (lane < 8) wsums[lane] = xv;           // inclusive warp totals
        if (lane == 7) d_bsum[blockIdx.x] = xv;   // block total
    }
    __syncthreads();
    int warp_excl = wid ? wsums[wid - 1] : 0;
    int t_excl = warp_excl + (ws - s3);
    if (base < N_NODES) {
        int4 p;
        p.x = t_excl;
        p.y = t_excl + s0;
        p.z = t_excl + s1;
        p.w = t_excl + s2;
        *(int4*)&d_ptr[base] = p;
        d_dinv[base + 0] = rsqrtf((float)(v.x + 1));
        d_dinv[base + 1] = rsqrtf((float)(v.y + 1));
        d_dinv[base + 2] = rsqrtf((float)(v.z + 1));
        d_dinv[base + 3] = rsqrtf((float)(v.w + 1));
    }
}

// add block offsets (per-thread loop over <=48 cached bsum entries), init cursors
__global__ void k_scan3() {
    int i = blockIdx.x * blockDim.x + threadIdx.x;
    if (i < N_NODES) {
        int blk = i >> 10;
        int off = 0;
        for (int b = 0; b < blk; b++) off += d_bsum[b];
        int p = d_ptr[i] + off;
        d_ptr[i] = p;
        d_cursor[i] = p;
    }
    if (i == 0) d_ptr[N_NODES] = N_EDGES;
}

__global__ void k_scatter(const int* __restrict__ ei) {
    int e = blockIdx.x * blockDim.x + threadIdx.x;
    if (e >= N_EDGES) return;
    int s = ei[e];
    int d = ei[N_EDGES + e];
    int p = atomicAdd(&d_cursor[d], 1);
    d_edge[p] = make_int2(s, __float_as_int(d_dinv[s] * d_dinv[d]));
}

// ---------------- merged parameter GEMM chain (single block, 3 phases) ----------------
__global__ void k_params(const float* __restrict__ W1, const float* __restrict__ b1,
                         const float* __restrict__ W2, const float* __restrict__ b2,
                         const float* __restrict__ W3, const float* __restrict__ b3,
                         const float* __restrict__ fc_w) {
    int tid = threadIdx.x;
    // phase 1: P3 = W3(160x128) @ fc_w(128x10); g3 = b3 @ fc_w
    for (int t = tid; t < HID * OUT_DIM + OUT_DIM; t += blockDim.x) {
        if (t < HID * OUT_DIM) {
            int i = t / OUT_DIM, c = t % OUT_DIM;
            float a = 0.f;
            for (int k = 0; k < OUT_C; k++) a += W3[i * OUT_C + k] * fc_w[k * OUT_DIM + c];
            d_P3[t] = a;
        } else {
            int c = t - HID * OUT_DIM;
            float a = 0.f;
            for (int k = 0; k < OUT_C; k++) a += b3[k] * fc_w[k * OUT_DIM + c];
            d_g3[c] = a;
        }
    }
    __syncthreads();
    // phase 2: P2 = W2(160x160) @ P3; g2 = b2 @ P3
    for (int t = tid; t < HID * OUT_DIM + OUT_DIM; t += blockDim.x) {
        if (t < HID * OUT_DIM) {
            int i = t / OUT_DIM, c = t % OUT_DIM;
            float a = 0.f;
            for (int k = 0; k < HID; k++) a += W2[i * HID + k] * d_P3[k * OUT_DIM + c];
            d_P2[t] = a;
        } else {
            int c = t - HID * OUT_DIM;
            float a = 0.f;
            for (int k = 0; k < HID; k++) a += b2[k] * d_P3[k * OUT_DIM + c];
            d_g2[c] = a;
        }
    }
    __syncthreads();
    // phase 3: R = W1(128x160) @ P2; g1 = b1 @ P2
    for (int t = tid; t < F_IN * OUT_DIM + OUT_DIM; t += blockDim.x) {
        if (t < F_IN * OUT_DIM) {
            int i = t / OUT_DIM, c = t % OUT_DIM;
            float a = 0.f;
            for (int k = 0; k < HID; k++) a += W1[i * HID + k] * d_P2[k * OUT_DIM + c];
            d_R[t] = a;
        } else {
            int c = t - F_IN * OUT_DIM;
            float a = 0.f;
            for (int k = 0; k < HID; k++) a += b1[k] * d_P2[k * OUT_DIM + c];
            d_g1[c] = a;
        }
    }
}

// ---------------- initial projection: H0 halves = [X@R (10), ones, 0...] ----------------
__global__ void k_init(const float* __restrict__ x) {
    __shared__ float sR[F_IN * OUT_DIM];   // 5 KB
    for (int i = threadIdx.x; i < F_IN * OUT_DIM; i += blockDim.x) sR[i] = d_R[i];
    __syncthreads();
    int t = blockIdx.x * blockDim.x + threadIdx.x;
    int node = t >> 1;
    if (node >= N_NODES) return;
    int q = t & 1;
    const float4* xr = (const float4*)(x + node * F_IN);
    float a[8] = {0, 0, 0, 0, 0, 0, 0, 0};
    if (q == 0) {
        #pragma unroll 4
        for (int k = 0; k < F_IN / 4; k++) {
            float4 xv = xr[k];
            const float* r0 = &sR[(4 * k) * OUT_DIM];
            #pragma unroll
            for (int j = 0; j < 8; j++)
                a[j] += xv.x * r0[j] + xv.y * r0[OUT_DIM + j]
                      + xv.z * r0[2 * OUT_DIM + j] + xv.w * r0[3 * OUT_DIM + j];
        }
    } else {
        #pragma unroll 4
        for (int k = 0; k < F_IN / 4; k++) {
            float4 xv = xr[k];
            const float* r0 = &sR[(4 * k) * OUT_DIM + 8];
            #pragma unroll
            for (int j = 0; j < 2; j++)
                a[j] += xv.x * r0[j] + xv.y * r0[OUT_DIM + j]
                      + xv.z * r0[2 * OUT_DIM + j] + xv.w * r0[3 * OUT_DIM + j];
        }
        a[2] = 1.0f;   // ones channel (global channel 10)
    }
    uint4 o;
    half2* op = (half2*)&o;
    #pragma unroll
    for (int i = 0; i < 4; i++) op[i] = __floats2half2_rn(a[2 * i], a[2 * i + 1]);
    d_Hh0[node * 2 + q] = o;
}

// ---------------- propagation ----------------
__device__ __forceinline__ void acc8(float* a, uint4 r, float w) {
    const half2* hp = (const half2*)&r;
    #pragma unroll
    for (int i = 0; i < 4; i++) {
        float2 f = __half22float2(hp[i]);
        a[2 * i]     += w * f.x;
        a[2 * i + 1] += w * f.y;
    }
}

// pair (2 threads) per dst node; each thread owns 8 halves (16B) of the 32B row.
// snap: 0 none, 1 -> c5 (from fp32 acc of channel 10), 2 -> c10.
__global__ void k_prop(int dir, int snap) {
    const uint4* __restrict__ h  = dir ? d_Hh1 : d_Hh0;
    uint4* __restrict__ out      = dir ? d_Hh0 : d_Hh1;
    int t = blockIdx.x * blockDim.x + threadIdx.x;
    int node = t >> 1;
    if (node >= N_NODES) return;
    int q = t & 1;
    int e = d_ptr[node], end = d_ptr[node + 1];

    float a[8] = {0, 0, 0, 0, 0, 0, 0, 0};
    float b[8] = {0, 0, 0, 0, 0, 0, 0, 0};
    for (; e + 1 < end; e += 2) {
        int2 m0 = d_edge[e];
        int2 m1 = d_edge[e + 1];
        uint4 r0 = h[(m0.x << 1) | q];
        uint4 r1 = h[(m1.x << 1) | q];
        acc8(a, r0, __int_as_float(m0.y));
        acc8(b, r1, __int_as_float(m1.y));
    }
    if (e < end) {
        int2 m0 = d_edge[e];
        uint4 r0 = h[(m0.x << 1) | q];
        acc8(a, r0, __int_as_float(m0.y));
    }
    float dn = d_dinv[node];
    uint4 rs = h[(node << 1) | q];
    acc8(a, rs, dn * dn);
    #pragma unroll
    for (int i = 0; i < 8; i++) a[i] += b[i];

    if (snap && q) {                 // q==1 holds channels 8..15; a[2] == channel 10
        if (snap == 1) d_c5[node] = a[2];
        else           d_c10[node] = a[2];
    }

    uint4 o;
    half2* op = (half2*)&o;
    #pragma unroll
    for (int i = 0; i < 4; i++) op[i] = __floats2half2_rn(a[2 * i], a[2 * i + 1]);
    out[(node << 1) | q] = o;
}

// ---------------- pooling ----------------
__global__ void k_zeropool() {
    int i = blockIdx.x * blockDim.x + threadIdx.x;
    if (i < NGR * OUT_DIM) d_pooled[i] = 0.f;
    if (i < NGR) d_counts[i] = 0;
}

__global__ void k_pool(const int* __restrict__ batch) {
    __shared__ float sp[NGR * OUT_DIM];
    __shared__ int   sc[NGR];
    int tid = threadIdx.x;
    for (int i = tid; i < NGR * OUT_DIM; i += blockDim.x) sp[i] = 0.f;
    if (tid < NGR) sc[tid] = 0;
    __syncthreads();

    int n = blockIdx.x * blockDim.x + tid;
    if (n < N_NODES) {
        int b = batch[n];
        atomicAdd(&sc[b], 1);
        float a10 = d_c10[n], a5 = d_c5[n];
        uint4 r0 = d_Hh1[n * 2], r1 = d_Hh1[n * 2 + 1];   // final state after hop 15
        const half2* hp0 = (const half2*)&r0;
        const half2* hp1 = (const half2*)&r1;
        float hv[10];
        float2 f;
        f = __half22float2(hp0[0]); hv[0] = f.x; hv[1] = f.y;
        f = __half22float2(hp0[1]); hv[2] = f.x; hv[3] = f.y;
        f = __half22float2(hp0[2]); hv[4] = f.x; hv[5] = f.y;
        f = __half22float2(hp0[3]); hv[6] = f.x; hv[7] = f.y;
        f = __half22float2(hp1[0]); hv[8] = f.x; hv[9] = f.y;
        #pragma unroll
        for (int c = 0; c < OUT_DIM; c++) {
            float z = hv[c] + a10 * d_g1[c] + a5 * d_g2[c] + d_g3[c];
            atomicAdd(&sp[b * OUT_DIM + c], z);
        }
    }
    __syncthreads();
    for (int i = tid; i < NGR * OUT_DIM; i += blockDim.x)
        if (sp[i] != 0.f) atomicAdd(&d_pooled[i], sp[i]);
    if (tid < NGR && sc[tid]) atomicAdd(&d_counts[tid], sc[tid]);
}

// ---------------- final: mean, +fc_b, log_softmax ----------------
__global__ void k_final(const float* __restrict__ fc_b, float* __restrict__ out) {
    int g = threadIdx.x;
    if (g >= NGR) return;
    float cnt = (float)d_counts[g];
    if (cnt < 1.f) cnt = 1.f;
    float l[OUT_DIM];
    float m = -1e30f;
    #pragma unroll
    for (int c = 0; c < OUT_DIM; c++) {
        l[c] = d_pooled[g * OUT_DIM + c] / cnt + fc_b[c];
        m = fmaxf(m, l[c]);
    }
    float s = 0.f;
    #pragma unroll
    for (int c = 0; c < OUT_DIM; c++) s += expf(l[c] - m);
    float lse = m + logf(s);
    #pragma unroll
    for (int c = 0; c < OUT_DIM; c++) out[g * OUT_DIM + c] = l[c] - lse;
}

// ---------------- launch ----------------
extern "C" void kernel_launch(void* const* d_in, const int* in_sizes, int n_in,
                              void* d_out, int out_size) {
    (void)in_sizes; (void)n_in; (void)out_size;
    const float* x     = (const float*)d_in[0];
    const int*   ei    = (const int*)d_in[1];     // int32 (JAX x64 disabled)
    const int*   batch = (const int*)d_in[2];     // int32
    const float* W1    = (const float*)d_in[3];
    const float* b1    = (const float*)d_in[4];
    const float* W2    = (const float*)d_in[5];
    const float* b2    = (const float*)d_in[6];
    const float* W3    = (const float*)d_in[7];
    const float* b3    = (const float*)d_in[8];
    const float* fc_w  = (const float*)d_in[9];
    const float* fc_b  = (const float*)d_in[10];
    float* out = (float*)d_out;

    const int TB  = 256;
    const int gN  = (N_NODES + TB - 1) / TB;                // 196
    const int gE4 = (N_EDGES / 4 + TB - 1) / TB;            // 782
    const int gE  = (N_EDGES + TB - 1) / TB;                // 3125
    const int gP  = (N_NODES * 2 + TB - 1) / TB;            // 391

    // degrees / dinv / CSR
    k_zero_deg<<<gN, TB>>>();
    k_deg<<<gE4, TB>>>(ei);
    k_scan1<<<SCAN_NB, TB>>>();
    k_scan3<<<gN, TB>>>();
    k_scatter<<<gE, TB>>>(ei);
    // folded parameter chain + initial projection
    k_params<<<1, 1024>>>(W1, b1, W2, b2, W3, b3, fc_w);
    k_init<<<gP, TB>>>(x);
    // 15 hops, ping-pong Hh0 <-> Hh1, snapshots fused at hops 5 and 10
    int dir = 0;
    for (int h = 1; h <= 15; h++) {
        int snap = (h == 5) ? 1 : (h == 10) ? 2 : 0;
        k_prop<<<gP, TB>>>(dir, snap);
        dir ^= 1;
    }
    // pool + final
    k_zeropool<<<3, TB>>>();
    k_pool<<<gN, TB>>>(batch);
    k_final<<<1, NGR>>>(fc_b, out);
}